// round 17
// baseline (speedup 1.0000x reference)
#include <cuda_runtime.h>
#include <cuda_bf16.h>
#include <math.h>

#define B_DIM 64
#define N_DIM 4096
#define K_DIM 32
#define U_DIM 16
#define NUM_STEPS 8
#define BN (B_DIM * N_DIM)            // 262144 sites
#define NU (N_DIM * U_DIM)            // 65536 (GEMM K)
#define H1 256
#define H2 32
#define NCLS 2
#define ROWLEN (K_DIM + 2)            // 34

#define NSPLIT 256
#define KCHUNK (NU / NSPLIT)          // 256
#define NTILE (KCHUNK / 16)           // 16 k-tiles per split
#define NGRP 16
#define SPG (NSPLIT / NGRP)

// scratch (device globals: allocation-free)
__device__ float g_h[BN * U_DIM];               // 16 MB
__device__ float g_part[NSPLIT * B_DIM * H1];   // 16 MB
__device__ float g_part2[NGRP * B_DIM * H1];    // 1 MB

__constant__ __align__(16) float cWn[K_DIM * U_DIM];
__constant__ __align__(16) float cWg[U_DIM * U_DIM];
__constant__ __align__(16) float cUg[U_DIM * U_DIM];
__constant__ __align__(16) float cWc[U_DIM * U_DIM];
__constant__ __align__(16) float cUc[U_DIM * U_DIM];
__constant__ __align__(16) float cWe[U_DIM * U_DIM];
__constant__ __align__(16) float cb[3 * U_DIM];   // bg | bc | be

__device__ __forceinline__ float tanh_hw(float v) {
    float r;
    asm("tanh.approx.f32 %0, %1;" : "=f"(r) : "f"(v));
    return r;
}
__device__ __forceinline__ float sigmoid_hw(float v) {
    return fmaf(0.5f, tanh_hw(0.5f * v), 0.5f);
}

__device__ __forceinline__ void mma_bf16(float* d, const unsigned* a, const unsigned* b) {
    asm volatile("mma.sync.aligned.m16n8k16.row.col.f32.bf16.bf16.f32 "
        "{%0,%1,%2,%3}, {%4,%5,%6,%7}, {%8,%9}, {%0,%1,%2,%3};"
        : "+f"(d[0]), "+f"(d[1]), "+f"(d[2]), "+f"(d[3])
        : "r"(a[0]), "r"(a[1]), "r"(a[2]), "r"(a[3]), "r"(b[0]), "r"(b[1]));
}

// pack two fp32 -> bf16x2 (f0 in low half)
__device__ __forceinline__ unsigned pack2bf(float f0, float f1) {
    unsigned r;
    asm("cvt.rn.bf16x2.f32 %0, %1, %2;" : "=r"(r) : "f"(f1), "f"(f0));
    return r;
}
// hi/lo split of a pair
__device__ __forceinline__ void split2(float f0, float f1, unsigned& hi, unsigned& lo) {
    hi = pack2bf(f0, f1);
    float h0 = __uint_as_float(hi << 16);
    float h1 = __uint_as_float(hi & 0xFFFF0000u);
    lo = pack2bf(f0 - h0, f1 - h1);
}
// split an 8-state (A/D-ordered) into 4 hi + 4 lo packed regs
__device__ __forceinline__ void split8(const float* s, unsigned* hi, unsigned* lo) {
#pragma unroll
    for (int i = 0; i < 4; i++) split2(s[2 * i], s[2 * i + 1], hi[i], lo[i]);
}

// ---------------------------------------------------------------------------
// Kernel 1: UGRNN on tensor cores. Warp = 16 sites (one m16 tile).
// State kept in mma fragment order: S[0..7] = {(g,c0),(g,c0+1),(g+8,c0),
// (g+8,c0+1), (g,c0+8),(g,c0+9),(g+8,c0+8),(g+8,c0+9)}, where g=lane/4,
// c0=(lane%4)*2. D fragments of the 2 n-tile MMAs map 1:1 onto this order,
// which is also the A-fragment order for the next step.
// ---------------------------------------------------------------------------
__global__ __launch_bounds__(256, 2)
void ugrnn_kernel(const float* __restrict__ inputs)
{
    __shared__ float sIn[128 * ROWLEN];   // 128 sites x 34 floats = 17408 B

    const int tid = threadIdx.x;
    const int warp = tid >> 5;
    const int lane = tid & 31;
    const int g = lane >> 2;          // 0..7
    const int q = lane & 3;           // 0..3
    const int c0 = q * 2;

    // stage inputs for this block's 128 sites (coalesced)
    {
        const float* src = inputs + (long long)blockIdx.x * 128 * ROWLEN;
#pragma unroll
        for (int i = 0; i < 17; i++) {
            int idx = tid + i * 256;
            if (idx < 128 * ROWLEN) sIn[idx] = src[idx];
        }
    }

    // ---- load weight B-fragments (hi/lo), once ----
    // B-frag for W[k][n] (row-major, stride 16): ntile nt, col = nt*8 + g
    unsigned wgh[2][2], wgl[2][2], ugh[2][2], ugl[2][2];
    unsigned wch[2][2], wcl[2][2], uch[2][2], ucl[2][2];
    unsigned weh[2][2], wel[2][2];
    unsigned wnh[2][2][2], wnl[2][2][2];   // [ktile][ntile][reg]
#pragma unroll
    for (int nt = 0; nt < 2; nt++) {
        const int col = nt * 8 + g;
#pragma unroll
        for (int r = 0; r < 2; r++) {
            const int k0r = q * 2 + r * 8;
            split2(cWg[k0r * 16 + col], cWg[(k0r + 1) * 16 + col], wgh[nt][r], wgl[nt][r]);
            split2(cUg[k0r * 16 + col], cUg[(k0r + 1) * 16 + col], ugh[nt][r], ugl[nt][r]);
            split2(cWc[k0r * 16 + col], cWc[(k0r + 1) * 16 + col], wch[nt][r], wcl[nt][r]);
            split2(cUc[k0r * 16 + col], cUc[(k0r + 1) * 16 + col], uch[nt][r], ucl[nt][r]);
            split2(cWe[k0r * 16 + col], cWe[(k0r + 1) * 16 + col], weh[nt][r], wel[nt][r]);
#pragma unroll
            for (int kt = 0; kt < 2; kt++)
                split2(cWn[(kt * 16 + k0r) * 16 + col], cWn[(kt * 16 + k0r + 1) * 16 + col],
                       wnh[kt][nt][r], wnl[kt][nt][r]);
        }
    }
    // biases in D order: [c0, c0+1, c0+8, c0+9]
    float bg4[4] = {cb[c0], cb[c0 + 1], cb[c0 + 8], cb[c0 + 9]};
    float bc4[4] = {cb[16 + c0], cb[16 + c0 + 1], cb[16 + c0 + 8], cb[16 + c0 + 9]};
    float be4[4] = {cb[32 + c0], cb[32 + c0 + 1], cb[32 + c0 + 8], cb[32 + c0 + 9]};

    __syncthreads();

    const int sr = warp * 16 + g;     // local site row (this lane's "row g")
    const int sr8 = sr + 8;

    // ---- m = neigh @ Wn  (K=32: two k-tiles), fragment accumulate ----
    float m[8];
#pragma unroll
    for (int i = 0; i < 8; i++) m[i] = 0.0f;
#pragma unroll
    for (int kt = 0; kt < 2; kt++) {
        const int cb0 = 1 + kt * 16;
        unsigned ahi[4], alo[4];
        split2(sIn[sr * ROWLEN + cb0 + c0],      sIn[sr * ROWLEN + cb0 + c0 + 1], ahi[0], alo[0]);
        split2(sIn[sr8 * ROWLEN + cb0 + c0],     sIn[sr8 * ROWLEN + cb0 + c0 + 1], ahi[1], alo[1]);
        split2(sIn[sr * ROWLEN + cb0 + c0 + 8],  sIn[sr * ROWLEN + cb0 + c0 + 9], ahi[2], alo[2]);
        split2(sIn[sr8 * ROWLEN + cb0 + c0 + 8], sIn[sr8 * ROWLEN + cb0 + c0 + 9], ahi[3], alo[3]);
#pragma unroll
        for (int nt = 0; nt < 2; nt++) {
            mma_bf16(m + nt * 4, ahi, wnh[kt][nt]);
            mma_bf16(m + nt * 4, ahi, wnl[kt][nt]);
            mma_bf16(m + nt * 4, alo, wnh[kt][nt]);
        }
    }

    // ---- init h, e (broadcast of h0/e0 across units) ----
    const float h0a = sIn[sr * ROWLEN], h0b = sIn[sr8 * ROWLEN];
    const float e0a = sIn[sr * ROWLEN + K_DIM + 1], e0b = sIn[sr8 * ROWLEN + K_DIM + 1];
    float h[8] = {h0a, h0a, h0b, h0b, h0a, h0a, h0b, h0b};
    float e[8] = {e0a, e0a, e0b, e0b, e0a, e0a, e0b, e0b};

#pragma unroll 1
    for (int step = 0; step < NUM_STEPS; step++) {
        // x = m + e; pack x and h hi/lo
        unsigned xhi[4], xlo[4], hhi[4], hlo[4];
        {
            float x[8];
#pragma unroll
            for (int i = 0; i < 8; i++) x[i] = m[i] + e[i];
            split8(x, xhi, xlo);
            split8(h, hhi, hlo);
        }

        // ---- g = sigmoid(x@Wg + h@Ug + bg) ----
        float gg[8];
        {
            float acc[8] = {bg4[0], bg4[1], bg4[0], bg4[1], bg4[2], bg4[3], bg4[2], bg4[3]};
#pragma unroll
            for (int nt = 0; nt < 2; nt++) {
                mma_bf16(acc + nt * 4, xhi, wgh[nt]);
                mma_bf16(acc + nt * 4, xhi, wgl[nt]);
                mma_bf16(acc + nt * 4, xlo, wgh[nt]);
                mma_bf16(acc + nt * 4, hhi, ugh[nt]);
                mma_bf16(acc + nt * 4, hhi, ugl[nt]);
                mma_bf16(acc + nt * 4, hlo, ugh[nt]);
            }
#pragma unroll
            for (int i = 0; i < 8; i++) gg[i] = sigmoid_hw(acc[i]);
        }

        // ---- c = tanh(x@Wc + h@Uc + bc); h = g*h + (1-g)*c ----
        {
            float acc[8] = {bc4[0], bc4[1], bc4[0], bc4[1], bc4[2], bc4[3], bc4[2], bc4[3]};
#pragma unroll
            for (int nt = 0; nt < 2; nt++) {
                mma_bf16(acc + nt * 4, xhi, wch[nt]);
                mma_bf16(acc + nt * 4, xhi, wcl[nt]);
                mma_bf16(acc + nt * 4, xlo, wch[nt]);
                mma_bf16(acc + nt * 4, hhi, uch[nt]);
                mma_bf16(acc + nt * 4, hhi, ucl[nt]);
                mma_bf16(acc + nt * 4, hlo, uch[nt]);
            }
#pragma unroll
            for (int i = 0; i < 8; i++) {
                float c = tanh_hw(acc[i]);
                h[i] = fmaf(gg[i], h[i] - c, c);
            }
        }

        // ---- e = tanh(x@We + be)  (skip on last step) ----
        if (step < NUM_STEPS - 1) {
            float acc[8] = {be4[0], be4[1], be4[0], be4[1], be4[2], be4[3], be4[2], be4[3]};
#pragma unroll
            for (int nt = 0; nt < 2; nt++) {
                mma_bf16(acc + nt * 4, xhi, weh[nt]);
                mma_bf16(acc + nt * 4, xhi, wel[nt]);
                mma_bf16(acc + nt * 4, xlo, weh[nt]);
            }
#pragma unroll
            for (int i = 0; i < 8; i++) e[i] = tanh_hw(acc[i]);
        }
    }

    // ---- write h fragments to g_h ----
    const long long s0 = (long long)blockIdx.x * 128 + sr;
    *(float2*)&g_h[s0 * U_DIM + c0]           = make_float2(h[0], h[1]);
    *(float2*)&g_h[(s0 + 8) * U_DIM + c0]     = make_float2(h[2], h[3]);
    *(float2*)&g_h[s0 * U_DIM + c0 + 8]       = make_float2(h[4], h[5]);
    *(float2*)&g_h[(s0 + 8) * U_DIM + c0 + 8] = make_float2(h[6], h[7]);
}

// ---------------------------------------------------------------------------
// Kernel 2: split-K GEMM on tensor cores (unchanged from R16).
// ---------------------------------------------------------------------------
__global__ __launch_bounds__(256, 2)
void gemm1_kernel(const float* __restrict__ W1)
{
    __shared__ __nv_bfloat16 sAhi[2][B_DIM][16];
    __shared__ __nv_bfloat16 sAlo[2][B_DIM][16];
    __shared__ __nv_bfloat16 sBhi[2][H1][16];
    __shared__ __nv_bfloat16 sBlo[2][H1][16];

    const int split = blockIdx.x;
    const int k0 = split * KCHUNK;
    const int tid = threadIdx.x;
    const int warp = tid >> 5;
    const int lane = tid & 31;
    const int qp = lane >> 2;
    const int rp = lane & 3;
    const int warpN = warp * 32;

    float acc[4][4][4];
#pragma unroll
    for (int i = 0; i < 4; i++)
#pragma unroll
        for (int j = 0; j < 4; j++)
#pragma unroll
            for (int q = 0; q < 4; q++) acc[i][j][q] = 0.0f;

    const int a_b = (tid >> 4);
    const int a_k = tid & 15;

    float pa[4], pb[16];

#pragma unroll
    for (int r = 0; r < 4; r++)
        pa[r] = g_h[(long long)(r * 16 + a_b) * NU + k0 + a_k];
#pragma unroll
    for (int r = 0; r < 16; r++)
        pb[r] = W1[(long long)(k0 + r) * H1 + tid];

    {
#pragma unroll
        for (int r = 0; r < 4; r++) {
            __nv_bfloat16 h = __float2bfloat16_rn(pa[r]);
            sAhi[0][r * 16 + a_b][a_k] = h;
            sAlo[0][r * 16 + a_b][a_k] = __float2bfloat16_rn(pa[r] - __bfloat162float(h));
        }
#pragma unroll
        for (int r = 0; r < 16; r++) {
            __nv_bfloat16 h = __float2bfloat16_rn(pb[r]);
            sBhi[0][tid][r] = h;
            sBlo[0][tid][r] = __float2bfloat16_rn(pb[r] - __bfloat162float(h));
        }
    }
    __syncthreads();

#pragma unroll 1
    for (int t = 0; t < NTILE; t++) {
        const int cur = t & 1;

        if (t + 1 < NTILE) {
            const int kk = (t + 1) * 16;
#pragma unroll
            for (int r = 0; r < 4; r++)
                pa[r] = g_h[(long long)(r * 16 + a_b) * NU + k0 + kk + a_k];
#pragma unroll
            for (int r = 0; r < 16; r++)
                pb[r] = W1[(long long)(k0 + kk + r) * H1 + tid];
        }

        unsigned bhi[4][2], blo[4][2];
#pragma unroll
        for (int nt = 0; nt < 4; nt++) {
            const int n = warpN + nt * 8 + qp;
            bhi[nt][0] = *(const unsigned*)&sBhi[cur][n][rp * 2];
            bhi[nt][1] = *(const unsigned*)&sBhi[cur][n][rp * 2 + 8];
            blo[nt][0] = *(const unsigned*)&sBlo[cur][n][rp * 2];
            blo[nt][1] = *(const unsigned*)&sBlo[cur][n][rp * 2 + 8];
        }

#pragma unroll
        for (int mt = 0; mt < 4; mt++) {
            const int r0 = mt * 16 + qp;
            unsigned ahi[4], alo[4];
            ahi[0] = *(const unsigned*)&sAhi[cur][r0][rp * 2];
            ahi[1] = *(const unsigned*)&sAhi[cur][r0 + 8][rp * 2];
            ahi[2] = *(const unsigned*)&sAhi[cur][r0][rp * 2 + 8];
            ahi[3] = *(const unsigned*)&sAhi[cur][r0 + 8][rp * 2 + 8];
            alo[0] = *(const unsigned*)&sAlo[cur][r0][rp * 2];
            alo[1] = *(const unsigned*)&sAlo[cur][r0 + 8][rp * 2];
            alo[2] = *(const unsigned*)&sAlo[cur][r0][rp * 2 + 8];
            alo[3] = *(const unsigned*)&sAlo[cur][r0 + 8][rp * 2 + 8];
#pragma unroll
            for (int nt = 0; nt < 4; nt++) {
                mma_bf16(acc[mt][nt], ahi, bhi[nt]);
                mma_bf16(acc[mt][nt], ahi, blo[nt]);
                mma_bf16(acc[mt][nt], alo, bhi[nt]);
            }
        }

        if (t + 1 < NTILE) {
            const int nxt = cur ^ 1;
#pragma unroll
            for (int r = 0; r < 4; r++) {
                __nv_bfloat16 h = __float2bfloat16_rn(pa[r]);
                sAhi[nxt][r * 16 + a_b][a_k] = h;
                sAlo[nxt][r * 16 + a_b][a_k] = __float2bfloat16_rn(pa[r] - __bfloat162float(h));
            }
#pragma unroll
            for (int r = 0; r < 16; r++) {
                __nv_bfloat16 h = __float2bfloat16_rn(pb[r]);
                sBhi[nxt][tid][r] = h;
                sBlo[nxt][tid][r] = __float2bfloat16_rn(pb[r] - __bfloat162float(h));
            }
            __syncthreads();
        }
    }

    float* __restrict__ out = g_part + (long long)split * (B_DIM * H1);
#pragma unroll
    for (int mt = 0; mt < 4; mt++) {
#pragma unroll
        for (int nt = 0; nt < 4; nt++) {
            const int r0 = mt * 16 + qp;
            const int c0 = warpN + nt * 8 + rp * 2;
            *(float2*)&out[r0 * H1 + c0]       = make_float2(acc[mt][nt][0], acc[mt][nt][1]);
            *(float2*)&out[(r0 + 8) * H1 + c0] = make_float2(acc[mt][nt][2], acc[mt][nt][3]);
        }
    }
}

// ---------------------------------------------------------------------------
__global__ __launch_bounds__(256, 4)
void reduce_kernel()
{
    const int blk = blockIdx.x;
    const int b = blk >> 4;
    const int grp = blk & 15;
    const int o = threadIdx.x;

    const float* __restrict__ p = g_part + ((long long)grp * SPG * B_DIM + b) * H1 + o;
    float s0 = 0.f, s1 = 0.f, s2 = 0.f, s3 = 0.f;
#pragma unroll
    for (int s = 0; s < SPG; s += 4) {
        s0 += p[(long long)(s + 0) * (B_DIM * H1)];
        s1 += p[(long long)(s + 1) * (B_DIM * H1)];
        s2 += p[(long long)(s + 2) * (B_DIM * H1)];
        s3 += p[(long long)(s + 3) * (B_DIM * H1)];
    }
    g_part2[((long long)grp * B_DIM + b) * H1 + o] = (s0 + s1) + (s2 + s3);
}

// ---------------------------------------------------------------------------
__global__ __launch_bounds__(256, 1)
void mlp_kernel(const float* __restrict__ b1,
                const float* __restrict__ W2,
                const float* __restrict__ b2,
                const float* __restrict__ W3,
                const float* __restrict__ b3,
                float* __restrict__ out)
{
    __shared__ float sv[H1];
    __shared__ float spart[8][H2];
    __shared__ float s2[H2];
    __shared__ float sl[NCLS];

    const int b = blockIdx.x;
    const int o = threadIdx.x;

    const float* __restrict__ p = g_part2 + (long long)b * H1 + o;
    float s0 = 0.f, s1 = 0.f, s2a = 0.f, s3 = 0.f;
#pragma unroll
    for (int s = 0; s < NGRP; s += 4) {
        s0  += p[(long long)(s + 0) * (B_DIM * H1)];
        s1  += p[(long long)(s + 1) * (B_DIM * H1)];
        s2a += p[(long long)(s + 2) * (B_DIM * H1)];
        s3  += p[(long long)(s + 3) * (B_DIM * H1)];
    }
    float v = b1[o] + ((s0 + s1) + (s2a + s3));
    sv[o] = fmaxf(v, 0.0f);
    __syncthreads();

    {
        const int col = o & 31;
        const int seg = o >> 5;
        float a = 0.0f;
#pragma unroll 8
        for (int i = 0; i < 32; i++) {
            int r = seg * 32 + i;
            a = fmaf(sv[r], __ldg(&W2[r * H2 + col]), a);
        }
        spart[seg][col] = a;
    }
    __syncthreads();

    if (o < H2) {
        float a = b2[o];
#pragma unroll
        for (int s = 0; s < 8; s++) a += spart[s][o];
        s2[o] = fmaxf(a, 0.0f);
    }
    __syncthreads();

    if (o < NCLS) {
        float a = b3[o];
#pragma unroll
        for (int j = 0; j < H2; j++)
            a = fmaf(s2[j], W3[j * NCLS + o], a);
        sl[o] = a;
    }
    __syncthreads();

    if (o == 0) {
        float mx = fmaxf(sl[0], sl[1]);
        float e0 = __expf(sl[0] - mx);
        float e1 = __expf(sl[1] - mx);
        float inv = __fdividef(1.0f, e0 + e1);
        out[b * NCLS + 0] = e0 * inv;
        out[b * NCLS + 1] = e1 * inv;
    }
}

// ---------------------------------------------------------------------------
extern "C" void kernel_launch(void* const* d_in, const int* in_sizes, int n_in,
                              void* d_out, int out_size)
{
    const float* inputs = (const float*)d_in[0];
    const float* Wn = (const float*)d_in[1];
    const float* Wg = (const float*)d_in[2];
    const float* Ug = (const float*)d_in[3];
    const float* bg = (const float*)d_in[4];
    const float* Wc = (const float*)d_in[5];
    const float* Uc = (const float*)d_in[6];
    const float* bc = (const float*)d_in[7];
    const float* We = (const float*)d_in[8];
    const float* be = (const float*)d_in[9];
    const float* W1 = (const float*)d_in[10];
    const float* b1 = (const float*)d_in[11];
    const float* W2 = (const float*)d_in[12];
    const float* b2 = (const float*)d_in[13];
    const float* W3 = (const float*)d_in[14];
    const float* b3 = (const float*)d_in[15];
    float* out = (float*)d_out;

    cudaMemcpyToSymbolAsync(cWn, Wn, K_DIM * U_DIM * sizeof(float), 0, cudaMemcpyDeviceToDevice, 0);
    cudaMemcpyToSymbolAsync(cWg, Wg, U_DIM * U_DIM * sizeof(float), 0, cudaMemcpyDeviceToDevice, 0);
    cudaMemcpyToSymbolAsync(cUg, Ug, U_DIM * U_DIM * sizeof(float), 0, cudaMemcpyDeviceToDevice, 0);
    cudaMemcpyToSymbolAsync(cWc, Wc, U_DIM * U_DIM * sizeof(float), 0, cudaMemcpyDeviceToDevice, 0);
    cudaMemcpyToSymbolAsync(cUc, Uc, U_DIM * U_DIM * sizeof(float), 0, cudaMemcpyDeviceToDevice, 0);
    cudaMemcpyToSymbolAsync(cWe, We, U_DIM * U_DIM * sizeof(float), 0, cudaMemcpyDeviceToDevice, 0);
    cudaMemcpyToSymbolAsync(cb, bg, U_DIM * sizeof(float), 0 * U_DIM * sizeof(float), cudaMemcpyDeviceToDevice, 0);
    cudaMemcpyToSymbolAsync(cb, bc, U_DIM * sizeof(float), 1 * U_DIM * sizeof(float), cudaMemcpyDeviceToDevice, 0);
    cudaMemcpyToSymbolAsync(cb, be, U_DIM * sizeof(float), 2 * U_DIM * sizeof(float), cudaMemcpyDeviceToDevice, 0);

    ugrnn_kernel<<<BN / 128, 256>>>(inputs);
    gemm1_kernel<<<NSPLIT, 256>>>(W1);
    reduce_kernel<<<B_DIM * NGRP, 256>>>();
    mlp_kernel<<<B_DIM, 256>>>(b1, W2, b2, W3, b3, out);
}